// round 1
// baseline (speedup 1.0000x reference)
#include <cuda_runtime.h>
#include <math.h>

// Problem constants
constexpr int T_ = 64;
constexpr int B_ = 256;
constexpr int NITEMS = 100000;
constexpr int E_ = 128;
constexpr int H_ = 512;
constexpr int NH_ = 8;
constexpr int HD_ = 64;
constexpr int G4_ = 4 * H_;   // 2048
constexpr int TB_ = T_ * B_;  // 16384

// ---------------- scratch (device globals; no allocation allowed) ----------
__device__ float g_embs[TB_ * E_];          // (T*B, E)  = emb[x]^2
__device__ float g_bsum[G4_];               // b_ih + b_hh
__device__ float g_Xg[TB_ * G4_];           // (T*B, 4H) input-gate preacts
__device__ float g_hbuf[2][B_ * H_];        // LSTM h ping-pong
__device__ float g_c[B_ * H_];              // LSTM c (in-place)
__device__ float g_lstm_out[TB_ * H_];      // (B, T, H) masked outputs
__device__ float g_Q[TB_ * H_];
__device__ float g_K[TB_ * H_];
__device__ float g_V[TB_ * H_];
__device__ float g_wout[TB_ * H_];          // attention output (B,T,H)
__device__ float g_mho[TB_ * H_];           // after output projection
__device__ float g_pooled[B_ * H_];
__device__ float g_ae[B_ * E_];

// ---------------- small kernels -------------------------------------------
__global__ void zero_init_kernel() {
    int i = blockIdx.x * blockDim.x + threadIdx.x;
    if (i < B_ * H_) { g_hbuf[0][i] = 0.f; g_c[i] = 0.f; }
}

__global__ void bias_sum_kernel(const float* __restrict__ b_ih,
                                const float* __restrict__ b_hh) {
    int i = blockIdx.x * blockDim.x + threadIdx.x;
    if (i < G4_) g_bsum[i] = b_ih[i] + b_hh[i];
}

// embs[t*B+b][:] = emb[x[t*B+b]][:]^2   (closest == emb[x], see analysis)
__global__ void gather_square_kernel(const int* __restrict__ x,
                                     const float* __restrict__ emb) {
    int fi = blockIdx.x * blockDim.x + threadIdx.x;   // float4 index
    int row = fi >> 5;                                // E/4 = 32 float4 per row
    int c4  = fi & 31;
    int id = x[row];
    float4 v = ((const float4*)(emb + (size_t)id * E_))[c4];
    float4 o;
    o.x = v.x * v.x; o.y = v.y * v.y; o.z = v.z * v.z; o.w = v.w * v.w;
    ((float4*)g_embs)[fi] = o;
}

// ---------------- generic SGEMM: C = A(MxK) * W(NxK)^T + bias --------------
__global__ __launch_bounds__(256)
void sgemm_nt(const float* __restrict__ A, const float* __restrict__ W,
              const float* __restrict__ bias, float* __restrict__ C,
              int M, int Ncols, int K) {
    __shared__ __align__(16) float As[8][128];
    __shared__ __align__(16) float Bs[8][128];
    const int tid = threadIdx.x;
    const int bm = blockIdx.y * 128;
    const int bn = blockIdx.x * 128;
    const int lr = tid >> 1;          // 0..127
    const int lk = (tid & 1) << 2;    // 0 or 4
    const int tx = tid & 15;
    const int ty = tid >> 4;
    const int arow = bm + lr;
    const int wrow = bn + lr;
    const bool aok = arow < M;
    const bool wok = wrow < Ncols;
    const float* Ap = A + (size_t)arow * K + lk;
    const float* Wp = W + (size_t)wrow * K + lk;

    float acc[8][8];
#pragma unroll
    for (int i = 0; i < 8; i++)
#pragma unroll
        for (int j = 0; j < 8; j++) acc[i][j] = 0.f;

    for (int k0 = 0; k0 < K; k0 += 8) {
        float4 av = make_float4(0.f, 0.f, 0.f, 0.f);
        float4 wv = make_float4(0.f, 0.f, 0.f, 0.f);
        if (aok) av = *(const float4*)(Ap + k0);
        if (wok) wv = *(const float4*)(Wp + k0);
        As[lk + 0][lr] = av.x; As[lk + 1][lr] = av.y;
        As[lk + 2][lr] = av.z; As[lk + 3][lr] = av.w;
        Bs[lk + 0][lr] = wv.x; Bs[lk + 1][lr] = wv.y;
        Bs[lk + 2][lr] = wv.z; Bs[lk + 3][lr] = wv.w;
        __syncthreads();
#pragma unroll
        for (int kk = 0; kk < 8; kk++) {
            float4 a0 = *(const float4*)&As[kk][ty * 8];
            float4 a1 = *(const float4*)&As[kk][ty * 8 + 4];
            float4 b0 = *(const float4*)&Bs[kk][tx * 8];
            float4 b1 = *(const float4*)&Bs[kk][tx * 8 + 4];
            float a[8] = {a0.x, a0.y, a0.z, a0.w, a1.x, a1.y, a1.z, a1.w};
            float bb[8] = {b0.x, b0.y, b0.z, b0.w, b1.x, b1.y, b1.z, b1.w};
#pragma unroll
            for (int i = 0; i < 8; i++)
#pragma unroll
                for (int j = 0; j < 8; j++) acc[i][j] += a[i] * bb[j];
        }
        __syncthreads();
    }
#pragma unroll
    for (int i = 0; i < 8; i++) {
        int m = bm + ty * 8 + i;
        if (m >= M) continue;
#pragma unroll
        for (int j = 0; j < 8; j++) {
            int n = bn + tx * 8 + j;
            if (n < Ncols) {
                float v = acc[i][j];
                if (bias) v += bias[n];
                C[(size_t)m * Ncols + n] = v;
            }
        }
    }
}

// ---------------- fused LSTM recurrent step --------------------------------
__device__ __forceinline__ float sigmoidf_(float x) {
    return 1.f / (1.f + expf(-x));
}

// Computes G = Xg_t + h_in @ w_hh^T, applies gates, writes h_out / c / out[t].
// Grid (H/32, B/32) = (16, 8) = 128 blocks, 256 threads.
__global__ __launch_bounds__(256)
void lstm_step_kernel(const float* __restrict__ Xg_t,    // (B, 4H)
                      const float* __restrict__ w_hh,    // (4H, H)
                      const float* __restrict__ h_in,    // (B, H)
                      float* __restrict__ h_out,         // (B, H)
                      const int* __restrict__ lengths,
                      int t) {
    __shared__ float hs[32][34];       // [k][b]
    __shared__ float ws[4][32][33];    // [gate][j][k]
    const int tid = threadIdx.x;
    const int tx = tid & 15, ty = tid >> 4;
    const int j0 = blockIdx.x * 32;
    const int b0 = blockIdx.y * 32;

    float acc[2][2][4];
#pragma unroll
    for (int a = 0; a < 2; a++)
#pragma unroll
        for (int b = 0; b < 2; b++)
#pragma unroll
            for (int g = 0; g < 4; g++) acc[a][b][g] = 0.f;

    const int hb = tid >> 3;           // 0..31
    const int hk = (tid & 7) << 2;     // 0..28

    for (int k0 = 0; k0 < H_; k0 += 32) {
        // load h tile (32b x 32k)
        float4 hv4 = *(const float4*)(h_in + (size_t)(b0 + hb) * H_ + k0 + hk);
        hs[hk + 0][hb] = hv4.x; hs[hk + 1][hb] = hv4.y;
        hs[hk + 2][hb] = hv4.z; hs[hk + 3][hb] = hv4.w;
        // load w tile (4 gates x 32j x 32k)
#pragma unroll
        for (int l = 0; l < 4; l++) {
            int fidx = tid + (l << 8);
            int row = fidx >> 3;           // 0..127
            int g = row >> 5, j = row & 31;
            int kq = (fidx & 7) << 2;
            float4 wv4 = *(const float4*)(w_hh + (size_t)(g * H_ + j0 + j) * H_ + k0 + kq);
            ws[g][j][kq + 0] = wv4.x; ws[g][j][kq + 1] = wv4.y;
            ws[g][j][kq + 2] = wv4.z; ws[g][j][kq + 3] = wv4.w;
        }
        __syncthreads();
#pragma unroll
        for (int kk = 0; kk < 32; kk++) {
            float h0v = hs[kk][ty];
            float h1v = hs[kk][ty + 16];
#pragma unroll
            for (int g = 0; g < 4; g++) {
                float w0 = ws[g][tx][kk];
                float w1 = ws[g][tx + 16][kk];
                acc[0][0][g] += h0v * w0;
                acc[0][1][g] += h0v * w1;
                acc[1][0][g] += h1v * w0;
                acc[1][1][g] += h1v * w1;
            }
        }
        __syncthreads();
    }

#pragma unroll
    for (int bi = 0; bi < 2; bi++) {
        int b = b0 + ty + 16 * bi;
        int len = lengths[b];
        const float* xg = Xg_t + (size_t)b * G4_;
#pragma unroll
        for (int ji = 0; ji < 2; ji++) {
            int j = j0 + tx + 16 * ji;
            float gi = sigmoidf_(acc[bi][ji][0] + xg[j]);
            float gf = sigmoidf_(acc[bi][ji][1] + xg[H_ + j]);
            float gg = tanhf(acc[bi][ji][2] + xg[2 * H_ + j]);
            float go = sigmoidf_(acc[bi][ji][3] + xg[3 * H_ + j]);
            float cn = gf * g_c[b * H_ + j] + gi * gg;
            g_c[b * H_ + j] = cn;
            float hn = go * tanhf(cn);
            h_out[b * H_ + j] = hn;
            g_lstm_out[(size_t)(b * T_ + t) * H_ + j] = (t < len) ? hn : 0.f;
        }
    }
}

// ---------------- attention: one block per (b, head) -----------------------
__global__ __launch_bounds__(256)
void attention_kernel(const float* __restrict__ Q,
                      const float* __restrict__ Kmat,
                      const float* __restrict__ V,
                      const int* __restrict__ lengths,
                      float* __restrict__ Wout) {
    __shared__ float qs[64 * 64];   // transposed [hd][r]; later aliased as vs [tk][hd]
    __shared__ float ks[64 * 64];   // transposed [hd][c]
    __shared__ float ss[64 * 64];   // scores [r][c]
    const int b = blockIdx.x, nh = blockIdx.y;
    const int tid = threadIdx.x;
    const int len = lengths[b];
    const size_t base = ((size_t)b * 64) * 512 + nh * 64;

    // load q,k transposed: fidx -> r = fidx&63, c4 = fidx>>6 (conflict-free STS)
#pragma unroll
    for (int l = 0; l < 4; l++) {
        int fidx = tid + (l << 8);
        int r = fidx & 63, c4 = fidx >> 6;
        float4 qv = *(const float4*)(Q + base + (size_t)r * 512 + c4 * 4);
        float4 kv = *(const float4*)(Kmat + base + (size_t)r * 512 + c4 * 4);
        qs[(c4 * 4 + 0) * 64 + r] = qv.x; qs[(c4 * 4 + 1) * 64 + r] = qv.y;
        qs[(c4 * 4 + 2) * 64 + r] = qv.z; qs[(c4 * 4 + 3) * 64 + r] = qv.w;
        ks[(c4 * 4 + 0) * 64 + r] = kv.x; ks[(c4 * 4 + 1) * 64 + r] = kv.y;
        ks[(c4 * 4 + 2) * 64 + r] = kv.z; ks[(c4 * 4 + 3) * 64 + r] = kv.w;
    }
    __syncthreads();

    const int tx = tid & 15, ty = tid >> 4;
    const int r0 = ty * 4, c0 = tx * 4;
    float acc[4][4];
#pragma unroll
    for (int i = 0; i < 4; i++)
#pragma unroll
        for (int j = 0; j < 4; j++) acc[i][j] = 0.f;

#pragma unroll 8
    for (int k = 0; k < 64; k++) {
        float4 aq = *(const float4*)&qs[k * 64 + r0];
        float4 bk = *(const float4*)&ks[k * 64 + c0];
        float a[4] = {aq.x, aq.y, aq.z, aq.w};
        float bb[4] = {bk.x, bk.y, bk.z, bk.w};
#pragma unroll
        for (int i = 0; i < 4; i++)
#pragma unroll
            for (int j = 0; j < 4; j++) acc[i][j] += a[i] * bb[j];
    }
#pragma unroll
    for (int i = 0; i < 4; i++)
#pragma unroll
        for (int j = 0; j < 4; j++) {
            int c = c0 + j;
            ss[(r0 + i) * 64 + c] = (c < len) ? acc[i][j] * 0.125f : -1e30f;
        }
    __syncthreads();

    // load V (row-major [tk][hd]) into qs region; softmax rows in parallel
    float* vs = qs;
#pragma unroll
    for (int l = 0; l < 4; l++) {
        int fidx = tid + (l << 8);
        int r = fidx >> 4, c4 = fidx & 15;
        ((float4*)vs)[fidx] = *(const float4*)(V + base + (size_t)r * 512 + c4 * 4);
    }
    if (tid < 64) {
        float m = -1e30f;
#pragma unroll 8
        for (int c = 0; c < 64; c++) m = fmaxf(m, ss[tid * 64 + c]);
        float s = 0.f;
#pragma unroll 8
        for (int c = 0; c < 64; c++) {
            float e = expf(ss[tid * 64 + c] - m);
            ss[tid * 64 + c] = e;
            s += e;
        }
        float inv = 1.f / s;
#pragma unroll 8
        for (int c = 0; c < 64; c++) ss[tid * 64 + c] *= inv;
    }
    __syncthreads();

    float o[4][4];
#pragma unroll
    for (int i = 0; i < 4; i++)
#pragma unroll
        for (int j = 0; j < 4; j++) o[i][j] = 0.f;
#pragma unroll 8
    for (int k = 0; k < 64; k++) {
        float a[4];
#pragma unroll
        for (int i = 0; i < 4; i++) a[i] = ss[(r0 + i) * 64 + k];
        float4 vv4 = *(const float4*)&vs[k * 64 + c0];
        float vv[4] = {vv4.x, vv4.y, vv4.z, vv4.w};
#pragma unroll
        for (int i = 0; i < 4; i++)
#pragma unroll
            for (int j = 0; j < 4; j++) o[i][j] += a[i] * vv[j];
    }
#pragma unroll
    for (int i = 0; i < 4; i++) {
        float4 ov = make_float4(o[i][0], o[i][1], o[i][2], o[i][3]);
        *(float4*)(Wout + base + (size_t)(r0 + i) * 512 + c0) = ov;
    }
}

// ---------------- pooling + hidden_to_embedding ----------------------------
__global__ void meanpool_kernel() {
    int idx = blockIdx.x * blockDim.x + threadIdx.x;  // < B*H
    int b = idx >> 9, j = idx & 511;
    float s = 0.f;
#pragma unroll 16
    for (int t = 0; t < 64; t++) s += g_mho[(size_t)(b * 64 + t) * 512 + j];
    g_pooled[idx] = s * (1.f / 64.f);
}

__global__ void h2e_kernel(const float* __restrict__ w_h2e,
                           const float* __restrict__ b_h2e) {
    __shared__ float sp[H_];
    int b = blockIdx.x, e = threadIdx.x;  // 128 threads
    for (int k = e; k < H_; k += 128) sp[k] = g_pooled[b * H_ + k];
    __syncthreads();
    float acc = b_h2e[e];
    const float* wr = w_h2e + (size_t)e * H_;
#pragma unroll 8
    for (int k = 0; k < H_; k++) acc += sp[k] * wr[k];
    g_ae[b * E_ + e] = acc;
}

// ---------------- entry point ----------------------------------------------
extern "C" void kernel_launch(void* const* d_in, const int* in_sizes, int n_in,
                              void* d_out, int out_size) {
    const int*   x       = (const int*)d_in[0];
    const int*   lengths = (const int*)d_in[1];
    const float* emb     = (const float*)d_in[2];
    const float* w_ih    = (const float*)d_in[3];
    const float* w_hh    = (const float*)d_in[4];
    const float* b_ih    = (const float*)d_in[5];
    const float* b_hh    = (const float*)d_in[6];
    const float* wq      = (const float*)d_in[7];
    const float* bq      = (const float*)d_in[8];
    const float* wk      = (const float*)d_in[9];
    const float* bk      = (const float*)d_in[10];
    const float* wv      = (const float*)d_in[11];
    const float* bv      = (const float*)d_in[12];
    const float* wo      = (const float*)d_in[13];
    const float* bo      = (const float*)d_in[14];
    const float* w_h2e   = (const float*)d_in[15];
    const float* b_h2e   = (const float*)d_in[16];
    float* out = (float*)d_out;

    float *p_embs, *p_bsum, *p_Xg, *p_h, *p_lo, *p_Q, *p_K, *p_V, *p_w, *p_mho, *p_pool, *p_ae;
    cudaGetSymbolAddress((void**)&p_embs, g_embs);
    cudaGetSymbolAddress((void**)&p_bsum, g_bsum);
    cudaGetSymbolAddress((void**)&p_Xg,   g_Xg);
    cudaGetSymbolAddress((void**)&p_h,    g_hbuf);
    cudaGetSymbolAddress((void**)&p_lo,   g_lstm_out);
    cudaGetSymbolAddress((void**)&p_Q,    g_Q);
    cudaGetSymbolAddress((void**)&p_K,    g_K);
    cudaGetSymbolAddress((void**)&p_V,    g_V);
    cudaGetSymbolAddress((void**)&p_w,    g_wout);
    cudaGetSymbolAddress((void**)&p_mho,  g_mho);
    cudaGetSymbolAddress((void**)&p_pool, g_pooled);
    cudaGetSymbolAddress((void**)&p_ae,   g_ae);
    float* p_h0 = p_h;
    float* p_h1 = p_h + B_ * H_;

    zero_init_kernel<<<(B_ * H_ + 255) / 256, 256>>>();
    bias_sum_kernel<<<(G4_ + 255) / 256, 256>>>(b_ih, b_hh);
    gather_square_kernel<<<(TB_ * E_ / 4 + 255) / 256, 256>>>(x, emb);

    // Xg = embs @ w_ih^T + (b_ih + b_hh)
    sgemm_nt<<<dim3(G4_ / 128, TB_ / 128), 256>>>(p_embs, w_ih, p_bsum, p_Xg, TB_, G4_, E_);

    // LSTM recurrence (64 sequential steps)
    for (int t = 0; t < T_; t++) {
        const float* hin = (t & 1) ? p_h1 : p_h0;
        float* hout      = (t & 1) ? p_h0 : p_h1;
        lstm_step_kernel<<<dim3(H_ / 32, B_ / 32), 256>>>(
            p_Xg + (size_t)t * B_ * G4_, w_hh, hin, hout, lengths, t);
    }

    // QKV projections
    sgemm_nt<<<dim3(H_ / 128, TB_ / 128), 256>>>(p_lo, wq, bq, p_Q, TB_, H_, H_);
    sgemm_nt<<<dim3(H_ / 128, TB_ / 128), 256>>>(p_lo, wk, bk, p_K, TB_, H_, H_);
    sgemm_nt<<<dim3(H_ / 128, TB_ / 128), 256>>>(p_lo, wv, bv, p_V, TB_, H_, H_);

    attention_kernel<<<dim3(B_, NH_), 256>>>(p_Q, p_K, p_V, lengths, p_w);

    // output projection
    sgemm_nt<<<dim3(H_ / 128, TB_ / 128), 256>>>(p_w, wo, bo, p_mho, TB_, H_, H_);

    meanpool_kernel<<<(B_ * H_ + 255) / 256, 256>>>();
    h2e_kernel<<<B_, 128>>>(w_h2e, b_h2e);

    // final scores = ae @ emb^T  (256 x 100000, K=128)
    sgemm_nt<<<dim3((NITEMS + 127) / 128, B_ / 128), 256>>>(p_ae, emb, nullptr, out, B_, NITEMS, E_);
}